// round 16
// baseline (speedup 1.0000x reference)
#include <cuda_runtime.h>
#include <stdint.h>

#define QN     256
#define DIM    128
#define NLIST  1024
#define MSUB   8
#define KCODE  256
#define DSUB   16
#define NPROBE 32
#define TOPK   100
#define MAXN   250000
#define CAP    10240
#define DYN_SMEM (CAP * 8)
#define NBLK   256            // build-phase chunking

typedef unsigned long long u64;
typedef unsigned int       u32;

// ---------------- device scratch (static: allocation-free) ------------------
__device__ float g_cnf[NLIST];            // centroid norms (XLA-reduce order)
__device__ float g_ct[DIM * NLIST];       // centroids transposed [d][l]
__device__ int   g_counts[NLIST];
__device__ int   g_starts[NLIST];
__device__ u32   g_bcnt[NBLK * NLIST];    // per-block list histograms (1 MB)
__device__ u32   g_bbase[NBLK * NLIST];   // per-block within-list offsets
__device__ int   g_inv[MAXN];             // point id per inverted slot
__device__ int4  g_codes[2 * MAXN];       // codes gathered into inverted order

// monotonic float->uint transform (total order preserving)
__device__ __forceinline__ u32 f2s(float f) {
    u32 u = __float_as_uint(f);
    return u ^ ((u >> 31) ? 0xFFFFFFFFu : 0x80000000u);
}

// XLA-GPU style row-norm (lane sums 4 contiguous rounded products, butterfly)
__device__ __forceinline__ float warp_norm128(const float* __restrict__ row, int lane)
{
    float p0 = __fmul_rn(row[4 * lane + 0], row[4 * lane + 0]);
    float p1 = __fmul_rn(row[4 * lane + 1], row[4 * lane + 1]);
    float p2 = __fmul_rn(row[4 * lane + 2], row[4 * lane + 2]);
    float p3 = __fmul_rn(row[4 * lane + 3], row[4 * lane + 3]);
    float s  = __fadd_rn(__fadd_rn(__fadd_rn(p0, p1), p2), p3);
    #pragma unroll
    for (int off = 16; off > 0; off >>= 1)
        s = __fadd_rn(s, __shfl_down_sync(0xFFFFFFFFu, s, off));
    return s;
}

// ---------------- build ------------------------------------------------------
__global__ void __launch_bounds__(256) k_prep(const float* __restrict__ centroids)
{
    int gw   = blockIdx.x * 8 + (threadIdx.x >> 5);
    int lane = threadIdx.x & 31;
    if (gw < NLIST) {
        float s = warp_norm128(centroids + (size_t)gw * DIM, lane);
        if (lane == 0) g_cnf[gw] = s;
    }
    int gtid = blockIdx.x * 256 + threadIdx.x;
    for (int i = gtid; i < DIM * NLIST; i += gridDim.x * 256) {
        int d = i >> 10, l = i & (NLIST - 1);
        g_ct[i] = __ldg(centroids + (size_t)l * DIM + d);
    }
}

// per-block histogram over a contiguous chunk of points
__global__ void __launch_bounds__(256) k_hist(const int* __restrict__ db_list, int N)
{
    __shared__ int sh[NLIST];
    int t = threadIdx.x, b = blockIdx.x;
    int ch   = (N + NBLK - 1) / NBLK;
    int lo   = b * ch;
    int hi   = min(N, lo + ch);
    for (int i = t; i < NLIST; i += 256) sh[i] = 0;
    __syncthreads();
    for (int n = lo + t; n < hi; n += 256)
        atomicAdd(&sh[db_list[n] & (NLIST - 1)], 1);
    __syncthreads();
    for (int i = t; i < NLIST; i += 256)
        g_bcnt[b * NLIST + i] = (u32)sh[i];
}

// per-list column scan over blocks -> per-block bases + list totals
__global__ void __launch_bounds__(256) k_colscan()
{
    int l = blockIdx.x * 256 + threadIdx.x;   // grid 4 x 256 = 1024 lists
    u32 acc = 0;
    #pragma unroll 4
    for (int b = 0; b < NBLK; ++b) {
        u32 v = g_bcnt[b * NLIST + l];
        g_bbase[b * NLIST + l] = acc;
        acc += v;
    }
    g_counts[l] = (int)acc;
}

__global__ void __launch_bounds__(1024) k_scan()
{
    __shared__ int s[NLIST];
    int t = threadIdx.x;
    int c = g_counts[t];
    s[t] = c;
    __syncthreads();
    for (int off = 1; off < NLIST; off <<= 1) {
        int v = (t >= off) ? s[t - off] : 0;
        __syncthreads();
        s[t] += v;
        __syncthreads();
    }
    g_starts[t] = s[t] - c;
}

// deterministic-offset scatter: no global atomics, coalesced loads
__global__ void __launch_bounds__(256) k_scatter(const int* __restrict__ db_list,
                                                 const int* __restrict__ db_codes,
                                                 int N)
{
    __shared__ int lcur[NLIST];
    int t = threadIdx.x, b = blockIdx.x;
    int ch = (N + NBLK - 1) / NBLK;
    int lo = b * ch;
    int hi = min(N, lo + ch);
    for (int i = t; i < NLIST; i += 256) lcur[i] = 0;
    __syncthreads();
    for (int n = lo + t; n < hi; n += 256) {
        int l = db_list[n] & (NLIST - 1);
        int r = atomicAdd(&lcur[l], 1);                    // cheap smem atomic
        int pos = g_starts[l] + (int)g_bbase[b * NLIST + l] + r;
        const int4* cp = (const int4*)(db_codes + (size_t)n * MSUB);
        g_inv[pos] = n;
        g_codes[2 * pos]     = __ldg(cp);
        g_codes[2 * pos + 1] = __ldg(cp + 1);
    }
}

// =============================================================================
// k_search: one CTA per query. Dynamic smem: CAP u64 candidate keys (80 KB),
// aliased as a 16K-bin histogram + 512-key buffer during the top-32 phase.
// =============================================================================
__global__ void __launch_bounds__(256) k_search(const float* __restrict__ queries,
                                                const float* __restrict__ codebooks,
                                                float* __restrict__ out)
{
    extern __shared__ u64 cand[];            // CAP keys / scratch

    __shared__ float lut[MSUB * KCODE];
    __shared__ float qsm[DIM];
    __shared__ u32   hist256[256];
    __shared__ u64   sel[128];
    __shared__ float s_qnf;
    __shared__ int   s_list[NPROBE], s_start[NPROBE], s_cn[NPROBE], s_pcum[NPROBE + 1];
    __shared__ int   s_cnt, s_k, s_bstar;
    __shared__ u32   s_pfx;

    int t = threadIdx.x;
    int q = blockIdx.x;

    if (t < DIM) qsm[t] = queries[q * DIM + t];
    if (t == 0) s_bstar = -1;
    __syncthreads();

    // ---------- phase 1: coarse distances, float4 coalesced reads ------------
    if (t < 32) {
        float s = warp_norm128(qsm, t);
        if (t == 0) s_qnf = s;
    }
    __syncthreads();
    float qnf = s_qnf;

    float a0 = 0.f, a1 = 0.f, a2 = 0.f, a3 = 0.f;   // seq FMA, d ascending
    #pragma unroll 8
    for (int d = 0; d < DIM; ++d) {
        float qd = qsm[d];
        float4 c = __ldg((const float4*)(g_ct + d * NLIST) + t);
        a0 = __fmaf_rn(qd, c.x, a0);
        a1 = __fmaf_rn(qd, c.y, a1);
        a2 = __fmaf_rn(qd, c.z, a2);
        a3 = __fmaf_rn(qd, c.w, a3);
    }
    int l0 = 4 * t;
    float4 cn4 = __ldg((const float4*)(g_cnf) + t);
    u64 key[4];
    key[0] = (((u64)f2s(__fsub_rn(__fadd_rn(qnf, cn4.x), __fmul_rn(2.f, a0)))) << 32) | (u32)(l0);
    key[1] = (((u64)f2s(__fsub_rn(__fadd_rn(qnf, cn4.y), __fmul_rn(2.f, a1)))) << 32) | (u32)(l0 + 1);
    key[2] = (((u64)f2s(__fsub_rn(__fadd_rn(qnf, cn4.z), __fmul_rn(2.f, a2)))) << 32) | (u32)(l0 + 2);
    key[3] = (((u64)f2s(__fsub_rn(__fadd_rn(qnf, cn4.w), __fmul_rn(2.f, a3)))) << 32) | (u32)(l0 + 3);

    // ---------- exact top-32 via 14-bit-prefix histogram select --------------
    {
        u32* h14  = (u32*)cand;                       // 16384 bins (64 KB)
        u64* selb = cand + 8192;                      // 512-key buffer
        #pragma unroll
        for (int i = 0; i < 64; ++i) h14[t * 64 + i] = 0;
        for (int i = t; i < 512; i += 256) selb[i] = ~0ULL;
        if (t == 0) s_cnt = 0;
        __syncthreads();
        #pragma unroll
        for (int s = 0; s < 4; ++s)
            atomicAdd(&h14[(u32)(key[s] >> 50)], 1u);
        __syncthreads();
        u32 part = 0;
        #pragma unroll
        for (int i = 0; i < 64; ++i) part += h14[t * 64 + i];
        hist256[t] = part;
        __syncthreads();
        for (int off = 1; off < 256; off <<= 1) {
            u32 v = (t >= off) ? hist256[t - off] : 0u;
            __syncthreads();
            hist256[t] += v;
            __syncthreads();
        }
        u32 cum  = hist256[t];
        u32 prev = cum - part;
        if ((int)prev < NPROBE && (int)cum >= NPROBE) {
            int c = (int)prev;
            #pragma unroll
            for (int i = 0; i < 64; ++i) {
                c += (int)h14[t * 64 + i];
                if (c >= NPROBE) { s_bstar = t * 64 + i; break; }
            }
        }
        __syncthreads();
        u32 bstar = (u32)s_bstar;
        #pragma unroll
        for (int s = 0; s < 4; ++s) {
            if ((u32)(key[s] >> 50) <= bstar) {
                int pos = atomicAdd(&s_cnt, 1);
                if (pos < 512) selb[pos] = key[s];
            }
        }
        __syncthreads();
        // bitonic sort 512 keys with 256 threads (2 elements/thread/stage)
        for (int kk = 2; kk <= 512; kk <<= 1) {
            for (int jj = kk >> 1; jj > 0; jj >>= 1) {
                #pragma unroll
                for (int e = t; e < 512; e += 256) {
                    int ixj = e ^ jj;
                    if (ixj > e) {
                        u64 a = selb[e], b2 = selb[ixj];
                        bool up = ((e & kk) == 0);
                        if (up ? (a > b2) : (a < b2)) { selb[e] = b2; selb[ixj] = a; }
                    }
                }
                __syncthreads();
            }
        }
        if (t < NPROBE) {
            int l = (int)(selb[t] & (NLIST - 1));
            s_list[t] = l;
            s_start[t] = g_starts[l];
            s_cn[t]    = g_counts[l];
        }
        __syncthreads();
    }
    if (t == 0) {
        int acc = 0;
        for (int i = 0; i < NPROBE; ++i) { s_pcum[i] = acc; acc += s_cn[i]; }
        s_pcum[NPROBE] = acc;
    }

    // ---------- phase 2: ADC LUT (reference-order f32) -----------------------
    #pragma unroll
    for (int m = 0; m < MSUB; ++m) {
        const float* cb = codebooks + ((size_t)(m * KCODE + t)) * DSUB;
        const float* qm = qsm + m * DSUB;
        float cn = 0.f, qns = 0.f, dq = 0.f;
        #pragma unroll
        for (int d = 0; d < DSUB; ++d) {
            float c = __ldg(cb + d);
            cn  = __fadd_rn(cn,  __fmul_rn(c, c));
            qns = __fadd_rn(qns, __fmul_rn(qm[d], qm[d]));
            dq  = __fmaf_rn(qm[d], c, dq);
        }
        lut[m * KCODE + t] = __fsub_rn(__fadd_rn(qns, cn), __fmul_rn(2.f, dq));
    }
    __syncthreads();   // scratch dead; cand becomes candidate buffer

    // ---------- phase 3: single walk, keys at deterministic slots ------------
    int total = s_pcum[NPROBE];
    int C = (total < CAP) ? total : CAP;
    #pragma unroll 1
    for (int i = 0; i < NPROBE; ++i) {
        int base = s_start[i], cnt = s_cn[i], slot0 = s_pcum[i];
        for (int j = t; j < cnt; j += 256) {
            int slot = slot0 + j;
            if (slot >= CAP) break;
            int4 c0 = g_codes[2 * (base + j)];       // coalesced
            int4 c1 = g_codes[2 * (base + j) + 1];
            float dsum = lut[c0.x & 255];            // sequential f32, m = 0..7
            dsum = __fadd_rn(dsum, lut[KCODE     + (c0.y & 255)]);
            dsum = __fadd_rn(dsum, lut[2 * KCODE + (c0.z & 255)]);
            dsum = __fadd_rn(dsum, lut[3 * KCODE + (c0.w & 255)]);
            dsum = __fadd_rn(dsum, lut[4 * KCODE + (c1.x & 255)]);
            dsum = __fadd_rn(dsum, lut[5 * KCODE + (c1.y & 255)]);
            dsum = __fadd_rn(dsum, lut[6 * KCODE + (c1.z & 255)]);
            dsum = __fadd_rn(dsum, lut[7 * KCODE + (c1.w & 255)]);
            cand[slot] = (((u64)f2s(dsum)) << 32) | (u32)g_inv[base + j];
        }
    }
    __syncthreads();

    int ksel = (C < TOPK) ? C : TOPK;
    if (C == 0) {
        if (t < TOPK) out[q * TOPK + t] = 0.f;   // unreachable for this data
        return;
    }

    // ---------- phase 4a: exact radix select of ksel-th smallest dist key ----
    if (t == 0) { s_pfx = 0u; s_k = ksel; }
    int iters = (C + 255) >> 8;
    for (int pass = 3; pass >= 0; --pass) {
        __syncthreads();
        u32 prefix = s_pfx;
        int kk     = s_k;
        int shift  = pass * 8;
        u32 pmask  = (pass == 3) ? 0u : (0xFFFFFFFFu << (shift + 8));
        hist256[t] = 0;
        __syncthreads();
        for (int it = 0; it < iters; ++it) {
            int j = (it << 8) + t;
            u32 b = 0xFFFFFFFFu;
            if (j < C) {
                u32 dk = (u32)(cand[j] >> 32);
                if ((dk & pmask) == prefix)
                    b = (dk >> shift) & 0xFF;
            }
            unsigned am = __activemask();
            u32 mm = __match_any_sync(am, b);
            if (b != 0xFFFFFFFFu) {
                int leader = __ffs(mm) - 1;
                if ((t & 31) == leader) atomicAdd(&hist256[b], (u32)__popc(mm));
            }
        }
        __syncthreads();
        for (int off = 1; off < 256; off <<= 1) {
            u32 v = (t >= off) ? hist256[t - off] : 0u;
            __syncthreads();
            hist256[t] += v;
            __syncthreads();
        }
        u32 cum  = hist256[t];
        u32 prev = (t == 0) ? 0u : hist256[t - 1];
        if ((int)cum >= kk && (int)prev < kk) {
            s_pfx = prefix | ((u32)t << shift);
            s_k   = kk - (int)prev;
        }
    }
    __syncthreads();
    u32 kth = s_pfx;

    // ---------- phase 4b: compact (<= kth), bitonic sort 128, emit -----------
    if (t == 0) s_cnt = 0;
    if (t < 128) sel[t] = ~0ULL;
    __syncthreads();
    for (int j = t; j < C; j += 256) {
        u64 k = cand[j];
        if ((u32)(k >> 32) <= kth) {
            int pos = atomicAdd(&s_cnt, 1);
            if (pos < 128) sel[pos] = k;
        }
    }
    __syncthreads();

    for (int kk2 = 2; kk2 <= 128; kk2 <<= 1) {
        for (int jj = kk2 >> 1; jj > 0; jj >>= 1) {
            if (t < 128) {
                int ixj = t ^ jj;
                if (ixj > t) {
                    u64 a = sel[t], b = sel[ixj];
                    bool up = ((t & kk2) == 0);
                    if (up ? (a > b) : (a < b)) { sel[t] = b; sel[ixj] = a; }
                }
            }
            __syncthreads();
        }
    }

    // output buffer is float32 (indices exact below 2^24)
    if (t < TOPK) out[q * TOPK + t] = (float)(u32)(sel[t] & 0xFFFFFFFFu);
}

// =============================================================================
// launch — input mapping verified by round-7 diagnostics (dict order)
// =============================================================================
extern "C" void kernel_launch(void* const* d_in, const int* in_sizes, int n_in,
                              void* d_out, int out_size)
{
    const float* queries   = (const float*)d_in[0];
    const float* centroids = (const float*)d_in[1];
    const float* codebooks = (const float*)d_in[2];
    const int*   db_codes  = (const int*)d_in[3];
    const int*   db_list   = (const int*)d_in[4];
    int N = in_sizes[4];
    if (N <= 0 || N > MAXN) N = MAXN;
    float* out = (float*)d_out;

    cudaFuncSetAttribute(k_search, cudaFuncAttributeMaxDynamicSharedMemorySize,
                         DYN_SMEM);

    k_prep<<<256, 256>>>(centroids);
    k_hist<<<NBLK, 256>>>(db_list, N);
    k_colscan<<<4, 256>>>();
    k_scan<<<1, 1024>>>();
    k_scatter<<<NBLK, 256>>>(db_list, db_codes, N);
    k_search<<<QN, 256, DYN_SMEM>>>(queries, codebooks, out);
}

// round 17
// speedup vs baseline: 1.3975x; 1.3975x over previous
#include <cuda_runtime.h>
#include <stdint.h>

#define QN     256
#define DIM    128
#define NLIST  1024
#define MSUB   8
#define KCODE  256
#define DSUB   16
#define NPROBE 32
#define TOPK   100
#define MAXN   250000
#define CAP    10240
#define DYN_SMEM (CAP * 8)

typedef unsigned long long u64;
typedef unsigned int       u32;

// ---------------- device scratch (static: allocation-free) ------------------
__device__ float g_cnf[NLIST];                    // centroid norms
__device__ float g_ct[DIM * NLIST];               // centroids transposed [d][l]
__device__ float g_cbt[MSUB * DSUB * KCODE];      // codebooks transposed [m][d][k]
__device__ float g_cbn[MSUB * KCODE];             // codebook norms (seq order)
__device__ int   g_counts[NLIST];
__device__ int   g_starts[NLIST];
__device__ int   g_cursor[NLIST];
__device__ int   g_inv[MAXN];                     // point id per inverted slot
__device__ u64   g_pk[MAXN];                      // packed 8x8-bit codes per slot

// monotonic float->uint transform (total order preserving)
__device__ __forceinline__ u32 f2s(float f) {
    u32 u = __float_as_uint(f);
    return u ^ ((u >> 31) ? 0xFFFFFFFFu : 0x80000000u);
}

// XLA-GPU style row-norm (lane sums 4 contiguous rounded products, butterfly)
__device__ __forceinline__ float warp_norm128(const float* __restrict__ row, int lane)
{
    float p0 = __fmul_rn(row[4 * lane + 0], row[4 * lane + 0]);
    float p1 = __fmul_rn(row[4 * lane + 1], row[4 * lane + 1]);
    float p2 = __fmul_rn(row[4 * lane + 2], row[4 * lane + 2]);
    float p3 = __fmul_rn(row[4 * lane + 3], row[4 * lane + 3]);
    float s  = __fadd_rn(__fadd_rn(__fadd_rn(p0, p1), p2), p3);
    #pragma unroll
    for (int off = 16; off > 0; off >>= 1)
        s = __fadd_rn(s, __shfl_down_sync(0xFFFFFFFFu, s, off));
    return s;
}

// 3-barrier inclusive block scan of h[256] (256 threads)
__device__ __forceinline__ void block_scan256(u32* h, int t)
{
    __shared__ u32 ws[8];
    int lane = t & 31, w = t >> 5;
    u32 v = h[t];
    #pragma unroll
    for (int off = 1; off < 32; off <<= 1) {
        u32 n = __shfl_up_sync(0xFFFFFFFFu, v, off);
        if (lane >= off) v += n;
    }
    if (lane == 31) ws[w] = v;
    __syncthreads();
    if (t < 8) {
        u32 x = ws[t];
        #pragma unroll
        for (int off = 1; off < 8; off <<= 1) {
            u32 n = __shfl_up_sync(0xFFu, x, off);
            if (t >= off) x += n;
        }
        ws[t] = x;
    }
    __syncthreads();
    if (w > 0) v += ws[w - 1];
    h[t] = v;
    __syncthreads();
}

// ---------------- build ------------------------------------------------------
__global__ void __launch_bounds__(256) k_prep(const float* __restrict__ centroids,
                                              const float* __restrict__ codebooks)
{
    int gw   = blockIdx.x * 8 + (threadIdx.x >> 5);
    int lane = threadIdx.x & 31;
    if (gw < NLIST) {
        float s = warp_norm128(centroids + (size_t)gw * DIM, lane);
        if (lane == 0) g_cnf[gw] = s;
    }
    int gtid = blockIdx.x * 256 + threadIdx.x;
    // centroid transpose [d][l]
    for (int i = gtid; i < DIM * NLIST; i += gridDim.x * 256) {
        int d = i >> 10, l = i & (NLIST - 1);
        g_ct[i] = __ldg(centroids + (size_t)l * DIM + d);
    }
    // codebook transpose [m][d][k]
    for (int i = gtid; i < MSUB * DSUB * KCODE; i += gridDim.x * 256) {
        int m = i / (DSUB * KCODE);
        int r = i - m * (DSUB * KCODE);
        int d = r >> 8, k = r & 255;
        g_cbt[i] = __ldg(codebooks + ((size_t)(m * KCODE + k)) * DSUB + d);
    }
    // codebook norms, sequential fadd(fmul) order (bit-matches old LUT cn)
    if (gtid < MSUB * KCODE) {
        const float* cb = codebooks + (size_t)gtid * DSUB;
        float cn = 0.f;
        #pragma unroll
        for (int d = 0; d < DSUB; ++d) {
            float c = __ldg(cb + d);
            cn = __fadd_rn(cn, __fmul_rn(c, c));
        }
        g_cbn[gtid] = cn;
    }
    if (gtid < NLIST) g_counts[gtid] = 0;
}

__global__ void __launch_bounds__(256) k_hist(const int* __restrict__ db_list, int N)
{
    __shared__ int sh[NLIST];
    int t = threadIdx.x;
    for (int i = t; i < NLIST; i += 256) sh[i] = 0;
    __syncthreads();
    for (int n = blockIdx.x * 256 + t; n < N; n += gridDim.x * 256)
        atomicAdd(&sh[db_list[n] & (NLIST - 1)], 1);
    __syncthreads();
    for (int i = t; i < NLIST; i += 256)
        if (sh[i]) atomicAdd(&g_counts[i], sh[i]);
}

__global__ void __launch_bounds__(1024) k_scan()
{
    __shared__ int s[NLIST];
    int t = threadIdx.x;
    int c = g_counts[t];
    s[t] = c;
    __syncthreads();
    for (int off = 1; off < NLIST; off <<= 1) {
        int v = (t >= off) ? s[t - off] : 0;
        __syncthreads();
        s[t] += v;
        __syncthreads();
    }
    g_starts[t] = s[t] - c;
    g_cursor[t] = s[t] - c;
}

// scatter: packed codes (8B) + id (4B) per point
__global__ void __launch_bounds__(256) k_scatter(const int* __restrict__ db_list,
                                                 const int* __restrict__ db_codes,
                                                 int N)
{
    int n = blockIdx.x * 256 + threadIdx.x;
    if (n < N) {
        int l   = db_list[n] & (NLIST - 1);
        int pos = atomicAdd(&g_cursor[l], 1);
        const int4* cp = (const int4*)(db_codes + (size_t)n * MSUB);
        int4 c0 = __ldg(cp);
        int4 c1 = __ldg(cp + 1);
        u32 lo = (u32)(c0.x & 255) | ((u32)(c0.y & 255) << 8) |
                 ((u32)(c0.z & 255) << 16) | ((u32)(c0.w & 255) << 24);
        u32 hi = (u32)(c1.x & 255) | ((u32)(c1.y & 255) << 8) |
                 ((u32)(c1.z & 255) << 16) | ((u32)(c1.w & 255) << 24);
        g_pk[pos]  = ((u64)hi << 32) | lo;
        g_inv[pos] = n;
    }
}

// =============================================================================
// k_search: one CTA per query. Dynamic smem: CAP u64 candidate keys (80 KB).
// =============================================================================
__global__ void __launch_bounds__(256) k_search(const float* __restrict__ queries,
                                                float* __restrict__ out)
{
    extern __shared__ u64 cand[];            // CAP keys

    __shared__ float lut[MSUB * KCODE];
    __shared__ float qsm[DIM];
    __shared__ u32   hist256[256];
    __shared__ u64   sel[128];               // also 64-slot tie buffer for coarse
    __shared__ float s_qnf;
    __shared__ int   s_start[NPROBE], s_cn[NPROBE], s_pcum[NPROBE + 1];
    __shared__ int   s_cnt, s_k;
    __shared__ u32   s_pfx;

    int t = threadIdx.x;
    int q = blockIdx.x;

    if (t < DIM) qsm[t] = queries[q * DIM + t];
    __syncthreads();

    // ---------- phase 1: coarse distances, float4 coalesced reads ------------
    if (t < 32) {
        float s = warp_norm128(qsm, t);
        if (t == 0) s_qnf = s;
    }
    __syncthreads();
    float qnf = s_qnf;

    float a0 = 0.f, a1 = 0.f, a2 = 0.f, a3 = 0.f;   // seq FMA, d ascending
    #pragma unroll 8
    for (int d = 0; d < DIM; ++d) {
        float qd = qsm[d];
        float4 c = __ldg((const float4*)(g_ct + d * NLIST) + t);
        a0 = __fmaf_rn(qd, c.x, a0);
        a1 = __fmaf_rn(qd, c.y, a1);
        a2 = __fmaf_rn(qd, c.z, a2);
        a3 = __fmaf_rn(qd, c.w, a3);
    }
    int l0 = 4 * t;
    float4 cn4 = __ldg((const float4*)(g_cnf) + t);
    u64 key[4];
    key[0] = (((u64)f2s(__fsub_rn(__fadd_rn(qnf, cn4.x), __fmul_rn(2.f, a0)))) << 32) | (u32)(l0);
    key[1] = (((u64)f2s(__fsub_rn(__fadd_rn(qnf, cn4.y), __fmul_rn(2.f, a1)))) << 32) | (u32)(l0 + 1);
    key[2] = (((u64)f2s(__fsub_rn(__fadd_rn(qnf, cn4.z), __fmul_rn(2.f, a2)))) << 32) | (u32)(l0 + 2);
    key[3] = (((u64)f2s(__fsub_rn(__fadd_rn(qnf, cn4.w), __fmul_rn(2.f, a3)))) << 32) | (u32)(l0 + 3);

    // ---------- exact top-32: radix select on 32-bit dist + tie sort ---------
    {
        if (t == 0) { s_pfx = 0u; s_k = NPROBE; }
        for (int pass = 3; pass >= 0; --pass) {
            __syncthreads();
            u32 prefix = s_pfx;
            int kk     = s_k;
            int shift  = pass * 8;
            u32 pmask  = (pass == 3) ? 0u : (0xFFFFFFFFu << (shift + 8));
            hist256[t] = 0;
            __syncthreads();
            #pragma unroll
            for (int s = 0; s < 4; ++s) {
                u32 dk = (u32)(key[s] >> 32);
                if ((dk & pmask) == prefix)
                    atomicAdd(&hist256[(dk >> shift) & 0xFF], 1u);
            }
            __syncthreads();
            block_scan256(hist256, t);
            u32 cum  = hist256[t];
            u32 prev = (t == 0) ? 0u : hist256[t - 1];
            if ((int)cum >= kk && (int)prev < kk) {
                s_pfx = prefix | ((u32)t << shift);
                s_k   = kk - (int)prev;
            }
        }
        __syncthreads();
        u32 kthd = s_pfx;                     // 32nd smallest distance value
        if (t == 0) s_cnt = 0;
        if (t < 64) sel[t] = ~0ULL;
        __syncthreads();
        #pragma unroll
        for (int s = 0; s < 4; ++s) {
            if ((u32)(key[s] >> 32) <= kthd) {
                int pos = atomicAdd(&s_cnt, 1);
                if (pos < 64) sel[pos] = key[s];
            }
        }
        __syncthreads();
        // bitonic sort 64 (ties broken by list id in low bits) -> first 32
        for (int kk2 = 2; kk2 <= 64; kk2 <<= 1) {
            for (int jj = kk2 >> 1; jj > 0; jj >>= 1) {
                if (t < 64) {
                    int ixj = t ^ jj;
                    if (ixj > t) {
                        u64 a = sel[t], b = sel[ixj];
                        bool up = ((t & kk2) == 0);
                        if (up ? (a > b) : (a < b)) { sel[t] = b; sel[ixj] = a; }
                    }
                }
                __syncthreads();
            }
        }
        if (t < NPROBE) {
            int l = (int)(sel[t] & (NLIST - 1));
            s_start[t] = g_starts[l];
            s_cn[t]    = g_counts[l];
        }
        __syncthreads();
    }
    if (t == 0) {
        int acc = 0;
        for (int i = 0; i < NPROBE; ++i) { s_pcum[i] = acc; acc += s_cn[i]; }
        s_pcum[NPROBE] = acc;
    }

    // ---------- phase 2: ADC LUT, coalesced transposed codebook reads --------
    #pragma unroll
    for (int m = 0; m < MSUB; ++m) {
        const float* qm = qsm + m * DSUB;
        float qns = 0.f, dq = 0.f;
        #pragma unroll
        for (int d = 0; d < DSUB; ++d)
            qns = __fadd_rn(qns, __fmul_rn(qm[d], qm[d]));   // seq, as before
        #pragma unroll
        for (int d = 0; d < DSUB; ++d)
            dq = __fmaf_rn(qm[d], __ldg(g_cbt + (m * DSUB + d) * KCODE + t), dq);
        lut[m * KCODE + t] =
            __fsub_rn(__fadd_rn(qns, __ldg(g_cbn + m * KCODE + t)), __fmul_rn(2.f, dq));
    }
    __syncthreads();

    // ---------- phase 3: single walk, packed codes, deterministic slots ------
    int total = s_pcum[NPROBE];
    int C = (total < CAP) ? total : CAP;
    #pragma unroll 1
    for (int i = 0; i < NPROBE; ++i) {
        int base = s_start[i], cnt = s_cn[i], slot0 = s_pcum[i];
        for (int j = t; j < cnt; j += 256) {
            int slot = slot0 + j;
            if (slot >= CAP) break;
            u64 pk = __ldg(g_pk + base + j);             // coalesced 8B
            u32 lo = (u32)pk, hi = (u32)(pk >> 32);
            float dsum = lut[lo & 255];                  // sequential f32, m=0..7
            dsum = __fadd_rn(dsum, lut[KCODE     + ((lo >>  8) & 255)]);
            dsum = __fadd_rn(dsum, lut[2 * KCODE + ((lo >> 16) & 255)]);
            dsum = __fadd_rn(dsum, lut[3 * KCODE + ((lo >> 24)      )]);
            dsum = __fadd_rn(dsum, lut[4 * KCODE + (hi & 255)]);
            dsum = __fadd_rn(dsum, lut[5 * KCODE + ((hi >>  8) & 255)]);
            dsum = __fadd_rn(dsum, lut[6 * KCODE + ((hi >> 16) & 255)]);
            dsum = __fadd_rn(dsum, lut[7 * KCODE + ((hi >> 24)      )]);
            cand[slot] = (((u64)f2s(dsum)) << 32) | (u32)__ldg(g_inv + base + j);
        }
    }
    __syncthreads();

    int ksel = (C < TOPK) ? C : TOPK;
    if (C == 0) {
        if (t < TOPK) out[q * TOPK + t] = 0.f;   // unreachable for this data
        return;
    }

    // ---------- phase 4a: exact radix select of ksel-th smallest dist key ----
    if (t == 0) { s_pfx = 0u; s_k = ksel; }
    int iters = (C + 255) >> 8;
    for (int pass = 3; pass >= 0; --pass) {
        __syncthreads();
        u32 prefix = s_pfx;
        int kk     = s_k;
        int shift  = pass * 8;
        u32 pmask  = (pass == 3) ? 0u : (0xFFFFFFFFu << (shift + 8));
        hist256[t] = 0;
        __syncthreads();
        for (int it = 0; it < iters; ++it) {
            int j = (it << 8) + t;
            u32 b = 0xFFFFFFFFu;
            if (j < C) {
                u32 dk = (u32)(cand[j] >> 32);
                if ((dk & pmask) == prefix)
                    b = (dk >> shift) & 0xFF;
            }
            unsigned am = __activemask();
            u32 mm = __match_any_sync(am, b);
            if (b != 0xFFFFFFFFu) {
                int leader = __ffs(mm) - 1;
                if ((t & 31) == leader) atomicAdd(&hist256[b], (u32)__popc(mm));
            }
        }
        __syncthreads();
        block_scan256(hist256, t);
        u32 cum  = hist256[t];
        u32 prev = (t == 0) ? 0u : hist256[t - 1];
        if ((int)cum >= kk && (int)prev < kk) {
            s_pfx = prefix | ((u32)t << shift);
            s_k   = kk - (int)prev;
        }
    }
    __syncthreads();
    u32 kth = s_pfx;

    // ---------- phase 4b: compact (<= kth), bitonic sort 128, emit -----------
    if (t == 0) s_cnt = 0;
    if (t < 128) sel[t] = ~0ULL;
    __syncthreads();
    for (int j = t; j < C; j += 256) {
        u64 k = cand[j];
        if ((u32)(k >> 32) <= kth) {
            int pos = atomicAdd(&s_cnt, 1);
            if (pos < 128) sel[pos] = k;
        }
    }
    __syncthreads();

    for (int kk2 = 2; kk2 <= 128; kk2 <<= 1) {
        for (int jj = kk2 >> 1; jj > 0; jj >>= 1) {
            if (t < 128) {
                int ixj = t ^ jj;
                if (ixj > t) {
                    u64 a = sel[t], b = sel[ixj];
                    bool up = ((t & kk2) == 0);
                    if (up ? (a > b) : (a < b)) { sel[t] = b; sel[ixj] = a; }
                }
            }
            __syncthreads();
        }
    }

    // output buffer is float32 (indices exact below 2^24)
    if (t < TOPK) out[q * TOPK + t] = (float)(u32)(sel[t] & 0xFFFFFFFFu);
}

// =============================================================================
// launch — input mapping verified by round-7 diagnostics (dict order)
// =============================================================================
extern "C" void kernel_launch(void* const* d_in, const int* in_sizes, int n_in,
                              void* d_out, int out_size)
{
    const float* queries   = (const float*)d_in[0];
    const float* centroids = (const float*)d_in[1];
    const float* codebooks = (const float*)d_in[2];
    const int*   db_codes  = (const int*)d_in[3];
    const int*   db_list   = (const int*)d_in[4];
    int N = in_sizes[4];
    if (N <= 0 || N > MAXN) N = MAXN;
    float* out = (float*)d_out;

    cudaFuncSetAttribute(k_search, cudaFuncAttributeMaxDynamicSharedMemorySize,
                         DYN_SMEM);

    k_prep<<<256, 256>>>(centroids, codebooks);
    k_hist<<<256, 256>>>(db_list, N);
    k_scan<<<1, 1024>>>();
    k_scatter<<<(N + 255) / 256, 256>>>(db_list, db_codes, N);
    k_search<<<QN, 256, DYN_SMEM>>>(queries, out);
}